// round 2
// baseline (speedup 1.0000x reference)
#include <cuda_runtime.h>

#define BATCH 32
#define CCH   512
#define RCH   256
#define HWSZ  1024

// Scratch (device-global arrays: the sanctioned alloc-free workaround)
__device__ float g_fkey [BATCH * RCH * HWSZ];           // 32 MB  [b][r][n]
__device__ float g_fprod[BATCH * RCH * HWSZ];           // 32 MB  [b][r][m]
__device__ float g_fval [BATCH * CCH * HWSZ];           // 64 MB  [b][c][m]
__device__ float g_energy[(size_t)BATCH * HWSZ * HWSZ]; // 128 MB [b][n][m] (softmax in-place)

// ---------------------------------------------------------------------------
// Projection: out[b][o][n] = sum_c W[o][c] * x[b][c][n] + bias[o]
// Destination global selected at compile time (no cudaGetSymbolAddress on host).
// Tile 64x64, BK=16, 256 threads, 4x4 per thread.
// ---------------------------------------------------------------------------
template<int M, int WHICH>
__global__ __launch_bounds__(256)
void proj_kernel(const float* __restrict__ x,
                 const float* __restrict__ W,
                 const float* __restrict__ bias)
{
    float* out = (WHICH == 0) ? g_fkey : (WHICH == 1) ? g_fprod : g_fval;

    const int K = CCH;
    __shared__ float As[16][64];   // [k][m]
    __shared__ float Bs[16][64];   // [k][n]

    const int b  = blockIdx.z;
    const int m0 = blockIdx.y * 64;
    const int n0 = blockIdx.x * 64;
    const int tid = threadIdx.x;
    const int tx = tid & 15;       // n sub-tile
    const int ty = tid >> 4;       // m sub-tile

    const float* xb = x + b * (CCH * HWSZ);

    float acc[4][4] = {};

    for (int k0 = 0; k0 < K; k0 += 16) {
        // A load: W[m0 + tid/4][k0 + (tid%4)*4 ..] -> As[k][m] (transposed scatter)
        {
            const int m  = tid >> 2;
            const int kq = (tid & 3) * 4;
            float4 v = *reinterpret_cast<const float4*>(&W[(m0 + m) * K + k0 + kq]);
            As[kq + 0][m] = v.x; As[kq + 1][m] = v.y;
            As[kq + 2][m] = v.z; As[kq + 3][m] = v.w;
        }
        // B load: direct copy
        {
            const int kr = tid >> 4;
            const int nq = (tid & 15) * 4;
            *reinterpret_cast<float4*>(&Bs[kr][nq]) =
                *reinterpret_cast<const float4*>(&xb[(k0 + kr) * HWSZ + n0 + nq]);
        }
        __syncthreads();

        #pragma unroll
        for (int k = 0; k < 16; k++) {
            float a[4], bb[4];
            *reinterpret_cast<float4*>(a)  = *reinterpret_cast<const float4*>(&As[k][ty * 4]);
            *reinterpret_cast<float4*>(bb) = *reinterpret_cast<const float4*>(&Bs[k][tx * 4]);
            #pragma unroll
            for (int i = 0; i < 4; i++)
                #pragma unroll
                for (int j = 0; j < 4; j++)
                    acc[i][j] += a[i] * bb[j];
        }
        __syncthreads();
    }

    float* ob = out + b * (M * HWSZ);
    #pragma unroll
    for (int i = 0; i < 4; i++) {
        const float bi = bias[m0 + ty * 4 + i];
        float4 v = make_float4(acc[i][0] + bi, acc[i][1] + bi,
                               acc[i][2] + bi, acc[i][3] + bi);
        *reinterpret_cast<float4*>(&ob[(m0 + ty * 4 + i) * HWSZ + n0 + tx * 4]) = v;
    }
}

// ---------------------------------------------------------------------------
// Energy: E[b][n][m] = sum_r fkey[b][r][n] * fprod[b][r][m]
// TN GEMM: both operands read K-major -> direct smem copies, no transpose.
// ---------------------------------------------------------------------------
__global__ __launch_bounds__(256)
void energy_kernel()
{
    __shared__ float As[16][64];   // [r][n]
    __shared__ float Bs[16][64];   // [r][m]

    const int b  = blockIdx.z;
    const int n0 = blockIdx.y * 64;   // key pixel (output row)
    const int m0 = blockIdx.x * 64;   // prod pixel (output col)
    const int tid = threadIdx.x;
    const int tx = tid & 15;
    const int ty = tid >> 4;

    const float* Kb = g_fkey  + b * (RCH * HWSZ);
    const float* Pb = g_fprod + b * (RCH * HWSZ);

    float acc[4][4] = {};

    for (int k0 = 0; k0 < RCH; k0 += 16) {
        const int kr = tid >> 4;
        const int cq = (tid & 15) * 4;
        *reinterpret_cast<float4*>(&As[kr][cq]) =
            *reinterpret_cast<const float4*>(&Kb[(k0 + kr) * HWSZ + n0 + cq]);
        *reinterpret_cast<float4*>(&Bs[kr][cq]) =
            *reinterpret_cast<const float4*>(&Pb[(k0 + kr) * HWSZ + m0 + cq]);
        __syncthreads();

        #pragma unroll
        for (int k = 0; k < 16; k++) {
            float a[4], bb[4];
            *reinterpret_cast<float4*>(a)  = *reinterpret_cast<const float4*>(&As[k][ty * 4]);
            *reinterpret_cast<float4*>(bb) = *reinterpret_cast<const float4*>(&Bs[k][tx * 4]);
            #pragma unroll
            for (int i = 0; i < 4; i++)
                #pragma unroll
                for (int j = 0; j < 4; j++)
                    acc[i][j] += a[i] * bb[j];
        }
        __syncthreads();
    }

    float* Eb = g_energy + (size_t)b * HWSZ * HWSZ;
    #pragma unroll
    for (int i = 0; i < 4; i++) {
        *reinterpret_cast<float4*>(&Eb[(size_t)(n0 + ty * 4 + i) * HWSZ + m0 + tx * 4]) =
            *reinterpret_cast<float4*>(acc[i]);
    }
}

// ---------------------------------------------------------------------------
// Softmax over last axis (row length 1024), in place on g_energy.
// One block (256 threads) per row; 4 elements per thread.
// ---------------------------------------------------------------------------
__device__ __forceinline__ float block_reduce(float v, bool do_max)
{
    __shared__ float red[8];
    #pragma unroll
    for (int o = 16; o > 0; o >>= 1) {
        const float other = __shfl_xor_sync(0xffffffffu, v, o);
        v = do_max ? fmaxf(v, other) : (v + other);
    }
    const int wid = threadIdx.x >> 5;
    if ((threadIdx.x & 31) == 0) red[wid] = v;
    __syncthreads();
    float r = red[0];
    #pragma unroll
    for (int w = 1; w < 8; w++) r = do_max ? fmaxf(r, red[w]) : (r + red[w]);
    return r;
}

__global__ __launch_bounds__(256)
void softmax_kernel()
{
    float* p = g_energy + (size_t)blockIdx.x * HWSZ;
    const int tid = threadIdx.x;

    float v[4];
    float mx = -3.4e38f;
    #pragma unroll
    for (int i = 0; i < 4; i++) {
        v[i] = p[tid + i * 256];
        mx = fmaxf(mx, v[i]);
    }
    mx = block_reduce(mx, true);
    __syncthreads();   // shared red[] reused between the two reductions

    float s = 0.f;
    #pragma unroll
    for (int i = 0; i < 4; i++) {
        v[i] = __expf(v[i] - mx);
        s += v[i];
    }
    s = block_reduce(s, false);

    const float inv = 1.0f / s;
    #pragma unroll
    for (int i = 0; i < 4; i++) p[tid + i * 256] = v[i] * inv;
}

// ---------------------------------------------------------------------------
// Attended + residual:
// out[b][c][n] = x[b][c][n] + param * sum_m fval[b][c][m] * sim[b][n][m]
// ---------------------------------------------------------------------------
__global__ __launch_bounds__(256)
void attended_kernel(const float* __restrict__ x,
                     const float* __restrict__ param,
                     float* __restrict__ out)
{
    __shared__ float As[16][64];   // [m][c]
    __shared__ float Bs[16][64];   // [m][n]

    const int b  = blockIdx.z;
    const int c0 = blockIdx.y * 64;
    const int n0 = blockIdx.x * 64;
    const int tid = threadIdx.x;
    const int tx = tid & 15;       // n
    const int ty = tid >> 4;       // c

    const float* Vb = g_fval + b * (CCH * HWSZ);
    const float* Sb = g_energy + (size_t)b * HWSZ * HWSZ;

    float acc[4][4] = {};

    for (int k0 = 0; k0 < HWSZ; k0 += 16) {
        {   // V[c][m] -> As[m][c]
            const int c  = tid >> 2;
            const int mq = (tid & 3) * 4;
            float4 v = *reinterpret_cast<const float4*>(&Vb[(c0 + c) * HWSZ + k0 + mq]);
            As[mq + 0][c] = v.x; As[mq + 1][c] = v.y;
            As[mq + 2][c] = v.z; As[mq + 3][c] = v.w;
        }
        {   // S[n][m] -> Bs[m][n]
            const int n  = tid >> 2;
            const int mq = (tid & 3) * 4;
            float4 v = *reinterpret_cast<const float4*>(&Sb[(size_t)(n0 + n) * HWSZ + k0 + mq]);
            Bs[mq + 0][n] = v.x; Bs[mq + 1][n] = v.y;
            Bs[mq + 2][n] = v.z; Bs[mq + 3][n] = v.w;
        }
        __syncthreads();

        #pragma unroll
        for (int k = 0; k < 16; k++) {
            float a[4], bb[4];
            *reinterpret_cast<float4*>(a)  = *reinterpret_cast<const float4*>(&As[k][ty * 4]);
            *reinterpret_cast<float4*>(bb) = *reinterpret_cast<const float4*>(&Bs[k][tx * 4]);
            #pragma unroll
            for (int i = 0; i < 4; i++)
                #pragma unroll
                for (int j = 0; j < 4; j++)
                    acc[i][j] += a[i] * bb[j];
        }
        __syncthreads();
    }

    const float pscale = param[0];
    const float* xb = x   + b * (CCH * HWSZ);
    float*       ob = out + b * (CCH * HWSZ);
    #pragma unroll
    for (int i = 0; i < 4; i++) {
        const int row = (c0 + ty * 4 + i) * HWSZ + n0 + tx * 4;
        float4 xv = *reinterpret_cast<const float4*>(&xb[row]);
        float4 v  = make_float4(xv.x + pscale * acc[i][0],
                                xv.y + pscale * acc[i][1],
                                xv.z + pscale * acc[i][2],
                                xv.w + pscale * acc[i][3]);
        *reinterpret_cast<float4*>(&ob[row]) = v;
    }
}

// ---------------------------------------------------------------------------
extern "C" void kernel_launch(void* const* d_in, const int* in_sizes, int n_in,
                              void* d_out, int out_size)
{
    const float* x     = (const float*)d_in[0];
    const float* Wk    = (const float*)d_in[1];
    const float* bk    = (const float*)d_in[2];
    const float* Wp    = (const float*)d_in[3];
    const float* bp    = (const float*)d_in[4];
    const float* Wv    = (const float*)d_in[5];
    const float* bv    = (const float*)d_in[6];
    const float* param = (const float*)d_in[7];
    float* out = (float*)d_out;

    dim3 blk(256);

    // Projections (write to template-selected device globals)
    proj_kernel<RCH, 0><<<dim3(HWSZ / 64, RCH / 64, BATCH), blk>>>(x, Wk, bk);
    proj_kernel<RCH, 1><<<dim3(HWSZ / 64, RCH / 64, BATCH), blk>>>(x, Wp, bp);
    proj_kernel<CCH, 2><<<dim3(HWSZ / 64, CCH / 64, BATCH), blk>>>(x, Wv, bv);

    // Energy
    energy_kernel<<<dim3(HWSZ / 64, HWSZ / 64, BATCH), blk>>>();

    // Softmax (rows of 1024)
    softmax_kernel<<<dim3(BATCH * HWSZ), blk>>>();

    // Attended + residual
    attended_kernel<<<dim3(HWSZ / 64, CCH / 64, BATCH), blk>>>(x, param, out);
}